// round 3
// baseline (speedup 1.0000x reference)
#include <cuda_runtime.h>
#include <cuda_bf16.h>
#include <cstdint>

// Problem constants
#define BATCH 16
#define HGRID 64
#define WGRID 64
#define DIM   512
#define NTOK  (1 + HGRID * WGRID)     // 4097

// Tiling
#define CT        32                  // channels per block (16 ull lanes)
#define LANES     16
#define TILE      16                  // 16x16 spatial tile per block
#define TIN       22                  // TILE + 6 halo
#define SPOS      (TIN * TIN)         // 484
#define NW        49                  // 7x7 fused taps
#define THREADS   256                 // 16 lanes x 16 y-threads

#define SMEM_ULL  (SPOS * LANES + NW * LANES + LANES)  // 7744+784+16 = 8544
#define SMEM_BYTES (SMEM_ULL * 8)                      // 68352

typedef unsigned long long ull;

__device__ __forceinline__ ull fma2(ull a, ull b, ull c) {
    ull d;
    asm("fma.rn.f32x2 %0, %1, %2, %3;" : "=l"(d) : "l"(a), "l"(b), "l"(c));
    return d;
}

__device__ __forceinline__ ull pack2(float lo, float hi) {
    ull d;
    asm("mov.b64 %0, {%1, %2};" : "=l"(d) : "f"(lo), "f"(hi));
    return d;
}

// ---------------------------------------------------------------------------
// Single fused kernel: weight fusion + cls copy + 7x7 depthwise conv
// grid: (16 channel groups, 16 spatial tiles, 16 batch), 256 threads
// ---------------------------------------------------------------------------
__global__ void __launch_bounds__(THREADS, 2)
conv_kernel(const float* __restrict__ x,
            const float* __restrict__ w7, const float* __restrict__ b7,
            const float* __restrict__ w5, const float* __restrict__ b5,
            const float* __restrict__ w3, const float* __restrict__ b3,
            float* __restrict__ out) {
    extern __shared__ ull sm[];
    ull* s_in = sm;                    // [SPOS][LANES]
    ull* s_w  = sm + SPOS * LANES;     // [NW][LANES]
    ull* s_b  = s_w + NW * LANES;      // [LANES]

    const int tid  = threadIdx.x;
    const int lane = tid & (LANES - 1);
    const int pg   = tid >> 4;                     // 0..15

    const int c0 = blockIdx.x * CT;
    const int h0 = (blockIdx.y >> 2) * TILE;
    const int w0 = (blockIdx.y & 3) * TILE;
    const int b  = blockIdx.z;

    const ull* x64 = (const ull*)x;
    ull* o64       = (ull*)out;
    const int cl      = (c0 >> 1) + lane;          // ull index in channel dim
    const int tokbase = b * NTOK + 1;              // skip cls token

    // --- Fuse weights for this block's 32 channels: w7+pad(w5)+pad(w3)+I ---
    #pragma unroll
    for (int s = tid; s < NW * LANES; s += THREADS) {
        const int k  = s >> 4;
        const int sl = s & (LANES - 1);
        const int kr = k / 7, kc = k - kr * 7;
        const int c  = c0 + 2 * sl;
        float v0 = w7[c * 49 + k];
        float v1 = w7[(c + 1) * 49 + k];
        if (kr >= 1 && kr <= 5 && kc >= 1 && kc <= 5) {
            const int k5 = (kr - 1) * 5 + (kc - 1);
            v0 += w5[c * 25 + k5];
            v1 += w5[(c + 1) * 25 + k5];
        }
        if (kr >= 2 && kr <= 4 && kc >= 2 && kc <= 4) {
            const int k3 = (kr - 2) * 3 + (kc - 2);
            v0 += w3[c * 9 + k3];
            v1 += w3[(c + 1) * 9 + k3];
        }
        if (kr == 3 && kc == 3) { v0 += 1.0f; v1 += 1.0f; }
        s_w[s] = pack2(v0, v1);
    }
    if (tid < LANES) {
        const int c = c0 + 2 * tid;
        s_b[tid] = pack2(b7[c] + b5[c] + b3[c],
                         b7[c + 1] + b5[c + 1] + b3[c + 1]);
    }

    // --- cls token pass-through (one tile-block per (cgroup, batch)) ---
    if (blockIdx.y == 0 && tid < LANES) {
        const int off = (b * NTOK) * (DIM / 2) + (c0 >> 1) + tid;
        o64[off] = x64[off];
    }

    // --- Stage input tile (22x22 x 32ch) with zero-padded halo ---
    #pragma unroll 2
    for (int p = pg; p < SPOS; p += 16) {
        const int row = p / TIN;
        const int col = p - row * TIN;
        const int gh = h0 + row - 3;
        const int gw = w0 + col - 3;
        ull v = 0ull;
        if ((unsigned)gh < (unsigned)HGRID && (unsigned)gw < (unsigned)WGRID)
            v = x64[(tokbase + gh * WGRID + gw) * (DIM / 2) + cl];
        s_in[p * LANES + lane] = v;
    }

    __syncthreads();

    const ull bv = s_b[lane];

    // --- Each thread: one row-pair (2 rows x 8 cols) ---
    const int y  = tid >> 4;            // 0..15
    const int rp = y & 7;               // row pair 0..7
    const int q0 = (y >> 3) * 8;        // col half: 0 or 8
    const int or0 = 2 * rp;             // first output row

    ull a0[8], a1[8];
    #pragma unroll
    for (int c = 0; c < 8; ++c) { a0[c] = bv; a1[c] = bv; }

    #pragma unroll
    for (int ir = 0; ir < 8; ++ir) {    // input rows or0 .. or0+7
        const int srow = or0 + ir;      // 0..21
        ull in[14];
        #pragma unroll
        for (int j = 0; j < 14; ++j)
            in[j] = s_in[(srow * TIN + q0 + j) * LANES + lane];

        if (ir <= 6) {                  // row0, kr = ir
            #pragma unroll
            for (int kc = 0; kc < 7; ++kc) {
                const ull w = s_w[(ir * 7 + kc) * LANES + lane];
                #pragma unroll
                for (int c = 0; c < 8; ++c)
                    a0[c] = fma2(in[c + kc], w, a0[c]);
            }
        }
        if (ir >= 1) {                  // row1, kr = ir-1
            #pragma unroll
            for (int kc = 0; kc < 7; ++kc) {
                const ull w = s_w[((ir - 1) * 7 + kc) * LANES + lane];
                #pragma unroll
                for (int c = 0; c < 8; ++c)
                    a1[c] = fma2(in[c + kc], w, a1[c]);
            }
        }
    }

    // --- Store 2 rows x 8 cols ---
    const int row0 = (tokbase + (h0 + or0) * WGRID + (w0 + q0)) * (DIM / 2) + cl;
    const int row1 = row0 + WGRID * (DIM / 2);
    #pragma unroll
    for (int c = 0; c < 8; ++c) {
        o64[row0 + c * (DIM / 2)] = a0[c];
        o64[row1 + c * (DIM / 2)] = a1[c];
    }
}

// ---------------------------------------------------------------------------
extern "C" void kernel_launch(void* const* d_in, const int* in_sizes, int n_in,
                              void* d_out, int out_size) {
    const float* x  = (const float*)d_in[0];
    const float* w7 = (const float*)d_in[1];
    const float* b7 = (const float*)d_in[2];
    const float* w5 = (const float*)d_in[3];
    const float* b5 = (const float*)d_in[4];
    const float* w3 = (const float*)d_in[5];
    const float* b3 = (const float*)d_in[6];
    float* out = (float*)d_out;

    cudaFuncSetAttribute(conv_kernel,
                         cudaFuncAttributeMaxDynamicSharedMemorySize, SMEM_BYTES);

    dim3 grid(DIM / CT, (HGRID / TILE) * (WGRID / TILE), BATCH);  // 16,16,16
    conv_kernel<<<grid, THREADS, SMEM_BYTES>>>(x, w7, b7, w5, b5, w3, b3, out);
}

// round 4
// speedup vs baseline: 1.2656x; 1.2656x over previous
#include <cuda_runtime.h>
#include <cuda_bf16.h>
#include <cstdint>

// Problem constants
#define BATCH 16
#define HGRID 64
#define WGRID 64
#define DIM   512
#define NTOK  (1 + HGRID * WGRID)     // 4097

// Tiling
#define CT        32                  // channels per block (16 ull lanes)
#define LANES     16
#define TILE      16                  // 16x16 spatial tile per block
#define TIN       22                  // TILE + 6 halo
#define SPOS      (TIN * TIN)         // 484
#define SP        486                 // padded pos-stride per lane (ull) — bank-safe, 16B-align-safe
#define WP        66                  // weight stride per lane (7 rows x 8 + pad)
#define NW        49
#define THREADS   256

#define SMEM_ULL   (LANES * SP + LANES * WP)      // 7776 + 1056 = 8832
#define SMEM_BYTES (SMEM_ULL * 8)                 // 70656

typedef unsigned long long ull;

__device__ __forceinline__ ull fma2(ull a, ull b, ull c) {
    ull d;
    asm("fma.rn.f32x2 %0, %1, %2, %3;" : "=l"(d) : "l"(a), "l"(b), "l"(c));
    return d;
}

__device__ __forceinline__ ull pack2(float lo, float hi) {
    ull d;
    asm("mov.b64 %0, {%1, %2};" : "=l"(d) : "f"(lo), "f"(hi));
    return d;
}

// ---------------------------------------------------------------------------
// Single fused kernel: weight fusion + cls copy + 7x7 depthwise conv
// grid: (16 channel groups, 16 spatial tiles, 16 batch), 256 threads
// smem layout is position-major per channel-pair lane -> LDS.128 main loop.
// ---------------------------------------------------------------------------
__global__ void __launch_bounds__(THREADS, 3)
conv_kernel(const float* __restrict__ x,
            const float* __restrict__ w7, const float* __restrict__ b7,
            const float* __restrict__ w5, const float* __restrict__ b5,
            const float* __restrict__ w3, const float* __restrict__ b3,
            float* __restrict__ out) {
    extern __shared__ ull sm[];
    ull* s_in = sm;                    // [LANES][SP]   (pos-major)
    ull* s_w  = sm + LANES * SP;       // [LANES][WP]   (8 slots per kr row)

    const int tid  = threadIdx.x;
    const int lane = tid & (LANES - 1);
    const int pg   = tid >> 4;                     // 0..15

    const int c0 = blockIdx.x * CT;
    const int h0 = (blockIdx.y >> 2) * TILE;
    const int w0 = (blockIdx.y & 3) * TILE;
    const int b  = blockIdx.z;

    const ull* x64 = (const ull*)x;
    ull* o64       = (ull*)out;
    const int cl      = (c0 >> 1) + lane;          // ull index in channel dim
    const int tokbase = b * NTOK + 1;              // skip cls token

    // --- Fuse weights for this block's 32 channels: w7+pad(w5)+pad(w3)+I ---
    #pragma unroll 1
    for (int s = tid; s < NW * LANES; s += THREADS) {
        const int k  = s >> 4;
        const int sl = s & (LANES - 1);
        const int kr = k / 7, kc = k - kr * 7;
        const int c  = c0 + 2 * sl;
        float v0 = w7[c * 49 + k];
        float v1 = w7[(c + 1) * 49 + k];
        if (kr >= 1 && kr <= 5 && kc >= 1 && kc <= 5) {
            const int k5 = (kr - 1) * 5 + (kc - 1);
            v0 += w5[c * 25 + k5];
            v1 += w5[(c + 1) * 25 + k5];
        }
        if (kr >= 2 && kr <= 4 && kc >= 2 && kc <= 4) {
            const int k3 = (kr - 2) * 3 + (kc - 2);
            v0 += w3[c * 9 + k3];
            v1 += w3[(c + 1) * 9 + k3];
        }
        if (kr == 3 && kc == 3) { v0 += 1.0f; v1 += 1.0f; }
        s_w[sl * WP + kr * 8 + kc] = pack2(v0, v1);
    }

    // --- cls token pass-through ---
    if (blockIdx.y == 0 && tid < LANES) {
        const int off = (b * NTOK) * (DIM / 2) + (c0 >> 1) + tid;
        o64[off] = x64[off];
    }

    // --- Stage input tile (22x22 x 32ch), pos-major, zero-padded halo ---
    #pragma unroll 2
    for (int p = pg; p < SPOS; p += 16) {
        const int row = p / TIN;
        const int col = p - row * TIN;
        const int gh = h0 + row - 3;
        const int gw = w0 + col - 3;
        ull v = 0ull;
        if ((unsigned)gh < (unsigned)HGRID && (unsigned)gw < (unsigned)WGRID)
            v = x64[(tokbase + gh * WGRID + gw) * (DIM / 2) + cl];
        s_in[lane * SP + p] = v;
    }

    // --- Bias (direct from global; tiny, L2/L1 resident) ---
    const int cb = c0 + 2 * lane;
    const ull bv = pack2(b7[cb] + b5[cb] + b3[cb],
                         b7[cb + 1] + b5[cb + 1] + b3[cb + 1]);

    __syncthreads();

    // --- Each thread: one row-pair (2 rows x 8 cols), 2 channels ---
    const int y   = tid >> 4;           // 0..15
    const int rp  = y & 7;              // row pair 0..7
    const int q0  = (y >> 3) * 8;       // col half: 0 or 8
    const int or0 = 2 * rp;             // first output row

    const ull* inb = s_in + lane * SP;
    const ull* wb  = s_w + lane * WP;

    ull a0[8], a1[8];
    #pragma unroll
    for (int c = 0; c < 8; ++c) { a0[c] = bv; a1[c] = bv; }

    #pragma unroll
    for (int ir = 0; ir < 8; ++ir) {    // input rows or0 .. or0+7
        const int srow = or0 + ir;      // 0..21
        ull in[14];
        {
            const ulonglong2* ip =
                (const ulonglong2*)(inb + srow * TIN + q0);
            #pragma unroll
            for (int j = 0; j < 7; ++j) {
                ulonglong2 v = ip[j];
                in[2 * j]     = v.x;
                in[2 * j + 1] = v.y;
            }
        }

        if (ir <= 6) {                  // row0, kr = ir
            ull w[8];
            const ulonglong2* wp = (const ulonglong2*)(wb + ir * 8);
            #pragma unroll
            for (int j = 0; j < 4; ++j) {
                ulonglong2 v = wp[j];
                w[2 * j] = v.x; w[2 * j + 1] = v.y;
            }
            #pragma unroll
            for (int kc = 0; kc < 7; ++kc)
                #pragma unroll
                for (int c = 0; c < 8; ++c)
                    a0[c] = fma2(in[c + kc], w[kc], a0[c]);
        }
        if (ir >= 1) {                  // row1, kr = ir-1
            ull w[8];
            const ulonglong2* wp = (const ulonglong2*)(wb + (ir - 1) * 8);
            #pragma unroll
            for (int j = 0; j < 4; ++j) {
                ulonglong2 v = wp[j];
                w[2 * j] = v.x; w[2 * j + 1] = v.y;
            }
            #pragma unroll
            for (int kc = 0; kc < 7; ++kc)
                #pragma unroll
                for (int c = 0; c < 8; ++c)
                    a1[c] = fma2(in[c + kc], w[kc], a1[c]);
        }
    }

    // --- Store 2 rows x 8 cols ---
    const int row0 = (tokbase + (h0 + or0) * WGRID + (w0 + q0)) * (DIM / 2) + cl;
    const int row1 = row0 + WGRID * (DIM / 2);
    #pragma unroll
    for (int c = 0; c < 8; ++c) {
        o64[row0 + c * (DIM / 2)] = a0[c];
        o64[row1 + c * (DIM / 2)] = a1[c];
    }
}

// ---------------------------------------------------------------------------
extern "C" void kernel_launch(void* const* d_in, const int* in_sizes, int n_in,
                              void* d_out, int out_size) {
    const float* x  = (const float*)d_in[0];
    const float* w7 = (const float*)d_in[1];
    const float* b7 = (const float*)d_in[2];
    const float* w5 = (const float*)d_in[3];
    const float* b5 = (const float*)d_in[4];
    const float* w3 = (const float*)d_in[5];
    const float* b3 = (const float*)d_in[6];
    float* out = (float*)d_out;

    cudaFuncSetAttribute(conv_kernel,
                         cudaFuncAttributeMaxDynamicSharedMemorySize, SMEM_BYTES);

    dim3 grid(DIM / CT, (HGRID / TILE) * (WGRID / TILE), BATCH);  // 16,16,16
    conv_kernel<<<grid, THREADS, SMEM_BYTES>>>(x, w7, b7, w5, b5, w3, b3, out);
}

// round 5
// speedup vs baseline: 1.4172x; 1.1198x over previous
#include <cuda_runtime.h>
#include <cuda_bf16.h>
#include <cstdint>

// Problem constants
#define BATCH 16
#define HGRID 64
#define WGRID 64
#define DIM   512
#define NTOK  (1 + HGRID * WGRID)     // 4097

// Tiling: 32 rows x 16 cols spatial tile, 32 channels (16 ull lanes)
#define CT        32
#define LANES     16
#define TILE_H    32
#define TILE_W    16
#define TINH      (TILE_H + 6)        // 38
#define TINW      (TILE_W + 6)        // 22
#define SPOS      (TINH * TINW)       // 836
#define SP        838                 // lane stride (ull): 838*8 mod 128 = 48 -> conflict-free
#define WP        58                  // weight lane stride: 58*8 mod 128 = 80 -> conflict-free
#define NW        49
#define THREADS   512

#define SMEM_ULL   (LANES * SP + LANES * WP)      // 13408 + 928 = 14336
#define SMEM_BYTES (SMEM_ULL * 8)                 // 114688

typedef unsigned long long ull;

__device__ __forceinline__ ull fma2(ull a, ull b, ull c) {
    ull d;
    asm("fma.rn.f32x2 %0, %1, %2, %3;" : "=l"(d) : "l"(a), "l"(b), "l"(c));
    return d;
}

__device__ __forceinline__ ull pack2(float lo, float hi) {
    ull d;
    asm("mov.b64 %0, {%1, %2};" : "=l"(d) : "f"(lo), "f"(hi));
    return d;
}

// ---------------------------------------------------------------------------
// Single fused kernel: weight fusion + cls copy + 7x7 depthwise conv
// grid: (16 channel groups, 2x4 spatial tiles, 16 batch), 512 threads
// ---------------------------------------------------------------------------
__global__ void __launch_bounds__(THREADS, 2)
conv_kernel(const float* __restrict__ x,
            const float* __restrict__ w7, const float* __restrict__ b7,
            const float* __restrict__ w5, const float* __restrict__ b5,
            const float* __restrict__ w3, const float* __restrict__ b3,
            float* __restrict__ out) {
    extern __shared__ ull sm[];
    ull* s_in = sm;                    // [LANES][SP]  pos-major per lane
    ull* s_w  = sm + LANES * SP;       // [LANES][WP]  8 slots per kr row

    const int tid  = threadIdx.x;
    const int lane = tid & (LANES - 1);
    const int pg   = tid >> 4;                     // 0..31

    const int c0 = blockIdx.x * CT;
    const int h0 = (blockIdx.y >> 2) * TILE_H;
    const int w0 = (blockIdx.y & 3) * TILE_W;
    const int b  = blockIdx.z;

    const ull* x64 = (const ull*)x;
    ull* o64       = (ull*)out;
    const int cl      = (c0 >> 1) + lane;
    const int tokbase = b * NTOK + 1;              // skip cls token

    // --- Fuse weights: w7 + pad(w5) + pad(w3) + identity ---
    #pragma unroll 1
    for (int s = tid; s < NW * LANES; s += THREADS) {
        const int k  = s >> 4;
        const int sl = s & (LANES - 1);
        const int kr = k / 7, kc = k - kr * 7;
        const int c  = c0 + 2 * sl;
        float v0 = w7[c * 49 + k];
        float v1 = w7[(c + 1) * 49 + k];
        if (kr >= 1 && kr <= 5 && kc >= 1 && kc <= 5) {
            const int k5 = (kr - 1) * 5 + (kc - 1);
            v0 += w5[c * 25 + k5];
            v1 += w5[(c + 1) * 25 + k5];
        }
        if (kr >= 2 && kr <= 4 && kc >= 2 && kc <= 4) {
            const int k3 = (kr - 2) * 3 + (kc - 2);
            v0 += w3[c * 9 + k3];
            v1 += w3[(c + 1) * 9 + k3];
        }
        if (kr == 3 && kc == 3) { v0 += 1.0f; v1 += 1.0f; }
        s_w[sl * WP + kr * 8 + kc] = pack2(v0, v1);
    }

    // --- cls token pass-through ---
    if (blockIdx.y == 0 && tid < LANES) {
        const int off = (b * NTOK) * (DIM / 2) + (c0 >> 1) + tid;
        o64[off] = x64[off];
    }

    // --- Stage input tile (38x22 x 32ch), pos-major, zero-padded halo ---
    #pragma unroll 2
    for (int p = pg; p < SPOS; p += 32) {
        const int row = p / TINW;
        const int col = p - row * TINW;
        const int gh = h0 + row - 3;
        const int gw = w0 + col - 3;
        ull v = 0ull;
        if ((unsigned)gh < (unsigned)HGRID && (unsigned)gw < (unsigned)WGRID)
            v = x64[(tokbase + gh * WGRID + gw) * (DIM / 2) + cl];
        s_in[lane * SP + p] = v;
    }

    // --- Bias ---
    const int cb = c0 + 2 * lane;
    const ull bv = pack2(b7[cb] + b5[cb] + b3[cb],
                         b7[cb + 1] + b5[cb + 1] + b3[cb + 1]);

    __syncthreads();

    // --- Each thread: one row-pair (2 rows x 8 cols), 2 channels ---
    const int y   = tid >> 4;           // 0..31
    const int rp  = y & 15;             // row pair 0..15
    const int q0  = (y >> 4) * 8;       // col half: 0 or 8
    const int or0 = 2 * rp;

    const ull* inb = s_in + lane * SP;
    const ull* wb  = s_w + lane * WP;

    ull a0[8], a1[8];
    #pragma unroll
    for (int c = 0; c < 8; ++c) { a0[c] = bv; a1[c] = bv; }

    ull wbuf[2][8];                     // ping-pong weight rows

    #pragma unroll
    for (int ir = 0; ir < 8; ++ir) {    // input rows or0 .. or0+7
        const int srow = or0 + ir;
        ull in[14];
        {
            const ulonglong2* ip = (const ulonglong2*)(inb + srow * TINW + q0);
            #pragma unroll
            for (int j = 0; j < 7; ++j) {
                ulonglong2 v = ip[j];
                in[2 * j]     = v.x;
                in[2 * j + 1] = v.y;
            }
        }

        if (ir <= 6) {                  // load weight row ir, feed a0
            const ulonglong2* wp2 = (const ulonglong2*)(wb + ir * 8);
            #pragma unroll
            for (int j = 0; j < 4; ++j) {
                ulonglong2 v = wp2[j];
                wbuf[ir & 1][2 * j]     = v.x;
                wbuf[ir & 1][2 * j + 1] = v.y;
            }
            #pragma unroll
            for (int kc = 0; kc < 7; ++kc)
                #pragma unroll
                for (int c = 0; c < 8; ++c)
                    a0[c] = fma2(in[c + kc], wbuf[ir & 1][kc], a0[c]);
        }
        if (ir >= 1) {                  // weight row ir-1 already resident
            #pragma unroll
            for (int kc = 0; kc < 7; ++kc)
                #pragma unroll
                for (int c = 0; c < 8; ++c)
                    a1[c] = fma2(in[c + kc], wbuf[(ir - 1) & 1][kc], a1[c]);
        }
    }

    // --- Store 2 rows x 8 cols ---
    const int row0 = (tokbase + (h0 + or0) * WGRID + (w0 + q0)) * (DIM / 2) + cl;
    const int row1 = row0 + WGRID * (DIM / 2);
    #pragma unroll
    for (int c = 0; c < 8; ++c) {
        o64[row0 + c * (DIM / 2)] = a0[c];
        o64[row1 + c * (DIM / 2)] = a1[c];
    }
}

// ---------------------------------------------------------------------------
extern "C" void kernel_launch(void* const* d_in, const int* in_sizes, int n_in,
                              void* d_out, int out_size) {
    const float* x  = (const float*)d_in[0];
    const float* w7 = (const float*)d_in[1];
    const float* b7 = (const float*)d_in[2];
    const float* w5 = (const float*)d_in[3];
    const float* b5 = (const float*)d_in[4];
    const float* w3 = (const float*)d_in[5];
    const float* b3 = (const float*)d_in[6];
    float* out = (float*)d_out;

    cudaFuncSetAttribute(conv_kernel,
                         cudaFuncAttributeMaxDynamicSharedMemorySize, SMEM_BYTES);

    dim3 grid(DIM / CT, (HGRID / TILE_H) * (WGRID / TILE_W), BATCH);  // 16,8,16
    conv_kernel<<<grid, THREADS, SMEM_BYTES>>>(x, w7, b7, w5, b5, w3, b3, out);
}

// round 6
// speedup vs baseline: 1.4342x; 1.0120x over previous
#include <cuda_runtime.h>
#include <cuda_bf16.h>
#include <cstdint>

// Problem constants
#define BATCH 16
#define HGRID 64
#define WGRID 64
#define DIM   512
#define NTOK  (1 + HGRID * WGRID)     // 4097

// Tiling: 32 rows x 16 cols spatial tile, 32 channels (16 ull lanes)
#define CT        32
#define LANES     16
#define TILE_H    32
#define TILE_W    16
#define TINH      (TILE_H + 6)        // 38
#define TINW      (TILE_W + 6)        // 22
#define SPOS      (TINH * TINW)       // 836
#define SP        838                 // lane stride (ull): 838*8 mod 128 = 48 -> conflict-free
#define WP        58                  // weight lane stride: 58*8 mod 128 = 80 -> conflict-free
#define NW        49
#define THREADS   512

#define SMEM_ULL   (LANES * SP + LANES * WP)      // 13408 + 928 = 14336
#define SMEM_BYTES (SMEM_ULL * 8)                 // 114688

typedef unsigned long long ull;

__device__ __forceinline__ ull fma2(ull a, ull b, ull c) {
    ull d;
    asm("fma.rn.f32x2 %0, %1, %2, %3;" : "=l"(d) : "l"(a), "l"(b), "l"(c));
    return d;
}

__device__ __forceinline__ ull pack2(float lo, float hi) {
    ull d;
    asm("mov.b64 %0, {%1, %2};" : "=l"(d) : "f"(lo), "f"(hi));
    return d;
}

// ---------------------------------------------------------------------------
// Single fused kernel: weight fusion + cls copy + 7x7 depthwise conv
// grid: (16 channel groups, 2x4 spatial tiles, 16 batch), 512 threads
// ---------------------------------------------------------------------------
__global__ void __launch_bounds__(THREADS, 2)
conv_kernel(const float* __restrict__ x,
            const float* __restrict__ w7, const float* __restrict__ b7,
            const float* __restrict__ w5, const float* __restrict__ b5,
            const float* __restrict__ w3, const float* __restrict__ b3,
            float* __restrict__ out) {
    extern __shared__ ull sm[];
    ull* s_in = sm;                    // [LANES][SP]  pos-major per lane
    ull* s_w  = sm + LANES * SP;       // [LANES][WP]  8 slots per kr row

    const int tid  = threadIdx.x;
    const int lane = tid & (LANES - 1);
    const int pg   = tid >> 4;                     // 0..31

    const int c0 = blockIdx.x * CT;
    const int h0 = (blockIdx.y >> 2) * TILE_H;
    const int w0 = (blockIdx.y & 3) * TILE_W;
    const int b  = blockIdx.z;

    const ull* x64 = (const ull*)x;
    ull* o64       = (ull*)out;
    const int cl      = (c0 >> 1) + lane;
    const int tokbase = b * NTOK + 1;              // skip cls token

    // --- Fuse weights: w7 + pad(w5) + pad(w3) + identity ---
    #pragma unroll 1
    for (int s = tid; s < NW * LANES; s += THREADS) {
        const int k  = s >> 4;
        const int sl = s & (LANES - 1);
        const int kr = k / 7, kc = k - kr * 7;
        const int c  = c0 + 2 * sl;
        float v0 = w7[c * 49 + k];
        float v1 = w7[(c + 1) * 49 + k];
        if (kr >= 1 && kr <= 5 && kc >= 1 && kc <= 5) {
            const int k5 = (kr - 1) * 5 + (kc - 1);
            v0 += w5[c * 25 + k5];
            v1 += w5[(c + 1) * 25 + k5];
        }
        if (kr >= 2 && kr <= 4 && kc >= 2 && kc <= 4) {
            const int k3 = (kr - 2) * 3 + (kc - 2);
            v0 += w3[c * 9 + k3];
            v1 += w3[(c + 1) * 9 + k3];
        }
        if (kr == 3 && kc == 3) { v0 += 1.0f; v1 += 1.0f; }
        s_w[sl * WP + kr * 8 + kc] = pack2(v0, v1);
    }

    // --- cls token pass-through ---
    if (blockIdx.y == 0 && tid < LANES) {
        const int off = (b * NTOK) * (DIM / 2) + (c0 >> 1) + tid;
        o64[off] = x64[off];
    }

    // --- Stage input tile (38x22 x 32ch), pos-major, zero-padded halo.
    //     Incremental row/col/offset arithmetic: no div/mod in the loop. ---
    {
        const ull* xb = x64 + (size_t)tokbase * (DIM / 2) + cl;
        ull* sp = s_in + lane * SP;

        int col = pg;                  // column within tile row (0..21 after norm)
        int gh  = h0 - 3;              // absolute input row
        if (col >= TINW) { col -= TINW; gh++; }
        int off = gh * WGRID + (w0 - 3 + col);   // element offset (row-major 64x64)

        #pragma unroll 2
        for (int p = pg; p < SPOS; p += 32) {
            const int gw = w0 - 3 + col;
            ull v = 0ull;
            if ((unsigned)gh < (unsigned)HGRID && (unsigned)gw < (unsigned)WGRID)
                v = xb[(long)off * (DIM / 2)];
            sp[p] = v;
            // advance 32 positions: always wraps at least once (32 > 22)
            col += 32 - TINW;          // +10
            gh  += 1;
            off += 32 + (WGRID - TINW);  // +74
            if (col >= TINW) { col -= TINW; gh++; off += WGRID - TINW; }
        }
    }

    // --- Bias ---
    const int cb = c0 + 2 * lane;
    const ull bv = pack2(b7[cb] + b5[cb] + b3[cb],
                         b7[cb + 1] + b5[cb + 1] + b3[cb + 1]);

    __syncthreads();

    // --- Each thread: one row-pair (2 rows x 8 cols), 2 channels ---
    const int y   = tid >> 4;           // 0..31
    const int rp  = y & 15;             // row pair 0..15
    const int q0  = (y >> 4) * 8;       // col half: 0 or 8
    const int or0 = 2 * rp;

    const ull* inb = s_in + lane * SP;
    const ull* wb  = s_w + lane * WP;

    ull a0[8], a1[8];
    #pragma unroll
    for (int c = 0; c < 8; ++c) { a0[c] = bv; a1[c] = bv; }

    ull wbuf[2][8];                     // ping-pong weight rows

    #pragma unroll
    for (int ir = 0; ir < 8; ++ir) {    // input rows or0 .. or0+7
        const int srow = or0 + ir;
        ull in[14];
        {
            const ulonglong2* ip = (const ulonglong2*)(inb + srow * TINW + q0);
            #pragma unroll
            for (int j = 0; j < 7; ++j) {
                ulonglong2 v = ip[j];
                in[2 * j]     = v.x;
                in[2 * j + 1] = v.y;
            }
        }

        if (ir <= 6) {                  // load weight row ir, feed a0
            const ulonglong2* wp2 = (const ulonglong2*)(wb + ir * 8);
            #pragma unroll
            for (int j = 0; j < 4; ++j) {
                ulonglong2 v = wp2[j];
                wbuf[ir & 1][2 * j]     = v.x;
                wbuf[ir & 1][2 * j + 1] = v.y;
            }
            #pragma unroll
            for (int kc = 0; kc < 7; ++kc)
                #pragma unroll
                for (int c = 0; c < 8; ++c)
                    a0[c] = fma2(in[c + kc], wbuf[ir & 1][kc], a0[c]);
        }
        if (ir >= 1) {                  // weight row ir-1 already resident
            #pragma unroll
            for (int kc = 0; kc < 7; ++kc)
                #pragma unroll
                for (int c = 0; c < 8; ++c)
                    a1[c] = fma2(in[c + kc], wbuf[(ir - 1) & 1][kc], a1[c]);
        }
    }

    // --- Store 2 rows x 8 cols ---
    const int row0 = (tokbase + (h0 + or0) * WGRID + (w0 + q0)) * (DIM / 2) + cl;
    const int row1 = row0 + WGRID * (DIM / 2);
    #pragma unroll
    for (int c = 0; c < 8; ++c) {
        o64[row0 + c * (DIM / 2)] = a0[c];
        o64[row1 + c * (DIM / 2)] = a1[c];
    }
}

// ---------------------------------------------------------------------------
extern "C" void kernel_launch(void* const* d_in, const int* in_sizes, int n_in,
                              void* d_out, int out_size) {
    const float* x  = (const float*)d_in[0];
    const float* w7 = (const float*)d_in[1];
    const float* b7 = (const float*)d_in[2];
    const float* w5 = (const float*)d_in[3];
    const float* b5 = (const float*)d_in[4];
    const float* w3 = (const float*)d_in[5];
    const float* b3 = (const float*)d_in[6];
    float* out = (float*)d_out;

    cudaFuncSetAttribute(conv_kernel,
                         cudaFuncAttributeMaxDynamicSharedMemorySize, SMEM_BYTES);

    dim3 grid(DIM / CT, (HGRID / TILE_H) * (WGRID / TILE_W), BATCH);  // 16,8,16
    conv_kernel<<<grid, THREADS, SMEM_BYTES>>>(x, w7, b7, w5, b5, w3, b3, out);
}